// round 1
// baseline (speedup 1.0000x reference)
#include <cuda_runtime.h>

// ---------------- problem constants ----------------
namespace {
constexpr int BATCH   = 2048;
constexpr int NTIME   = 2048;
constexpr int SEASLEN = 2055;          // 7 + 1 + 2047
constexpr int W       = 288;           // len(arange(0, 2014, 7))
constexpr int CH      = 67;            // 28 (y_in) + 35 (X) + 4 (S)
constexpr long long INS_ELEMS  = (long long)W * BATCH * CH;  // 39,518,208
constexpr long long OUTS_ELEMS = (long long)W * BATCH * 7;   //  4,128,768
constexpr long long LEV_ELEMS  = (long long)BATCH * NTIME;   //  4,194,304
}

// scratch (no runtime allocation allowed)
__device__ float g_L[BATCH * NTIME];   // log(Y[b,t] / seasonal[b,t])
__device__ float g_LL[W * BATCH];      // log(levels[b, 7w+27]), [w][b]

// ---------------- kernel 1: sequential ES scan, one thread per batch row ----
__global__ void es_scan(const float* __restrict__ Y,
                        const int*   __restrict__ idxs,
                        const float* __restrict__ emb,
                        float* __restrict__ levels,     // [B][2048]
                        float* __restrict__ seasonal)   // [B][2055]
{
    int b = blockIdx.x * blockDim.x + threadIdx.x;
    if (b >= BATCH) return;

    const float* e = emb + (long long)idxs[b] * 9;
    float a   = 1.f / (1.f + __expf(-e[0]));   // lev_sms
    float bs  = 1.f / (1.f + __expf(-e[1]));   // seas_sms
    float am  = 1.f - a;
    float bsm = 1.f - bs;

    float is0 = __expf(e[2]);
    float buf[7];                               // rotated init: [is1..is6, is0]
#pragma unroll
    for (int j = 0; j < 6; j++) buf[j] = __expf(e[3 + j]);
    buf[6] = is0;

    const float* Yr  = Y        + (long long)b * NTIME;
    float* levr      = levels   + (long long)b * NTIME;
    float* sear      = seasonal + (long long)b * SEASLEN;
    float* Lr        = g_L      + (long long)b * NTIME;

    sear[0] = is0;
#pragma unroll
    for (int j = 0; j < 6; j++) sear[1 + j] = buf[j];
    sear[7] = is0;

    float lev = __fdividef(Yr[0], is0);
    levr[0] = lev;
    Lr[0]   = __logf(lev);                      // log(Y0/seasonal0) == log(level0)

    // 2047 steps = 292 groups of 7 + tail of 3. Unrolled-by-7 so buf[] indices
    // are static registers. Note: s at step k == seasonal[k+1], so L[k+1] = log(q).
    int k = 0;
    for (int g = 0; g < 292; g++) {
#pragma unroll
        for (int sl = 0; sl < 7; sl++) {
            float y  = Yr[k + 1];
            float s  = buf[sl];
            float q  = __fdividef(y, s);
            float nl = fmaf(a, q, am * lev);
            float ns = fmaf(bs, __fdividef(y, nl), bsm * s);
            buf[sl] = ns;
            lev     = nl;
            levr[k + 1] = nl;
            sear[8 + k] = ns;
            Lr[k + 1]   = __logf(q);
            if (sl == 5 && g >= 3 && g <= 290)   // t = k+1 = 7w+27
                g_LL[(g - 3) * BATCH + b] = __logf(nl);
            k++;
        }
    }
#pragma unroll
    for (int sl = 0; sl < 3; sl++) {             // k = 2044..2046 -> slots 0..2
        float y  = Yr[k + 1];
        float s  = buf[sl];
        float q  = __fdividef(y, s);
        float nl = fmaf(a, q, am * lev);
        float ns = fmaf(bs, __fdividef(y, nl), bsm * s);
        buf[sl] = ns;
        lev     = nl;
        levr[k + 1] = nl;
        sear[8 + k] = ns;
        Lr[k + 1]   = __logf(q);
        k++;
    }
}

// ---------------- kernel 2: insample windows (W, B, 67) ---------------------
__global__ void win_insample(const float* __restrict__ X,
                             const float* __restrict__ S,
                             float* __restrict__ out)
{
    int idx = blockIdx.x * blockDim.x + threadIdx.x;   // < 39,518,208
    int c  = idx % CH;
    int bw = idx / CH;
    int b  = bw & (BATCH - 1);
    int w  = bw >> 11;
    int ws = w * 7;
    float v;
    if (c < 28) {
        v = g_L[b * NTIME + ws + c] - g_LL[w * BATCH + b];
    } else if (c < 63) {
        v = X[b * NTIME + ws + (c - 28)];              // N_T == 1
    } else {
        v = S[(b << 2) + (c - 63)];
    }
    out[idx] = v;
}

// ---------------- kernel 3: outsample windows (W, B, 7) ---------------------
__global__ void win_outsample(const float* __restrict__ Y,
                              float* __restrict__ out)
{
    int idx = blockIdx.x * blockDim.x + threadIdx.x;   // < 4,128,768
    int j  = idx % 7;
    int bw = idx / 7;
    int b  = bw & (BATCH - 1);
    int w  = bw >> 11;
    out[idx] = Y[b * NTIME + w * 7 + 28 + j];
}

// ---------------- launch -----------------------------------------------------
extern "C" void kernel_launch(void* const* d_in, const int* in_sizes, int n_in,
                              void* d_out, int out_size)
{
    const float* S    = (const float*)d_in[0];   // (2048, 4)
    const float* Y    = (const float*)d_in[1];   // (2048, 2048)
    const float* X    = (const float*)d_in[2];   // (2048, 1, 2048)
    const int*   idxs = (const int*)  d_in[3];   // (2048,)
    const float* emb  = (const float*)d_in[4];   // (100000, 9)
    // d_in[5] = step_size (fixed 7; shapes baked into out_size)

    float* out      = (float*)d_out;
    float* ins      = out;                                   // 39,518,208
    float* outs     = out + INS_ELEMS;                       //  4,128,768
    float* levels   = out + INS_ELEMS + OUTS_ELEMS;          //  4,194,304
    float* seasonal = out + INS_ELEMS + OUTS_ELEMS + LEV_ELEMS; // 2048*2055

    es_scan<<<64, 32>>>(Y, idxs, emb, levels, seasonal);
    win_insample<<<(int)(INS_ELEMS / 256), 256>>>(X, S, ins);     // exact multiple
    win_outsample<<<(int)(OUTS_ELEMS / 256), 256>>>(Y, outs);     // exact multiple
}